// round 3
// baseline (speedup 1.0000x reference)
#include <cuda_runtime.h>
#include <math.h>
#include <stdint.h>

// Problem constants (fixed shapes from setup_inputs)
#define B      1024
#define L      128
#define KPOS   8
#define NNEG   2048
#define NW     (B*KPOS + NNEG)   // 10240 W rows
#define NR     (B + NW)          // 11264 total rows (queries then W)
#define ROW_W0 B                 // first W row
#define ROW_N0 (B + B*KPOS)     // first negative row = 9216
#define EDIM   256
#define H      4
#define HD     64
#define P      16
#define M      32
#define R      2
#define NUML   131072

// Quadrature constants (double precision folded at compile time)
#define SQRT2_D 1.4142135623730951
#define CC      2.000001
__device__ __constant__ float c_s[2] = { (float)((2.0 - SQRT2_D)/CC), (float)((2.0 + SQRT2_D)/CC) };
__device__ __constant__ float c_w[2] = { (float)((2.0 + SQRT2_D)/(4.0*CC)), (float)((2.0 - SQRT2_D)/(4.0*CC)) };
#define INV_SQRT_M 0.17677669253f   // 1/sqrt(32.000001)

// Scratch (static device globals: allocation-free)
__device__ float d_anchT[HD*P];            // normalized anchors, transposed [d][p]
__device__ float d_omT  [HD*R*H*M];        // omega/8, transposed [d][r*128+h*32+m]
__device__ float d_x    [(size_t)NR*EDIM]; // raw rows (pooled queries, gathered W)
__device__ float d_poly [(size_t)NR*H*P];  // [row][h*16+p]
__device__ float d_prf  [(size_t)NR*R*H*M];// [row][r*128+h*32+m]
__device__ float d_T    [R*H*P*M];         // [rh][p*32+m]
__device__ float d_numer[B];

__device__ __forceinline__ float warpsum(float v) {
    #pragma unroll
    for (int o = 16; o; o >>= 1) v += __shfl_xor_sync(0xffffffffu, v, o);
    return v;
}

// ---------------------------------------------------------------- prep: anchors + omega transpose + zero T
__global__ void prep_kernel(const float* __restrict__ anchors,
                            const float* __restrict__ omega) {
    int bx = blockIdx.x, t = threadIdx.x;   // 64 threads
    if (bx < P) {
        __shared__ float red[64];
        float v = anchors[bx*HD + t];
        red[t] = v*v;
        __syncthreads();
        for (int s = 32; s > 0; s >>= 1) { if (t < s) red[t] += red[t+s]; __syncthreads(); }
        d_anchT[t*P + bx] = v / sqrtf(red[0]);      // reference: no eps here
    } else if (bx < P + 256) {
        int e = (bx - P)*64 + t;                    // omega linear index [r][h][d][m]
        int m = e & 31, d = (e >> 5) & 63, h = (e >> 11) & 3, r = e >> 13;
        d_omT[d*256 + r*128 + h*32 + m] = omega[e] * 0.125f;   // fold /sqrt(HD)
    } else {
        d_T[(bx - (P + 256))*64 + t] = 0.f;
    }
}

// ---------------------------------------------------------------- query pooling (raw, un-normalized)
__global__ void pool_kernel(const int* __restrict__ indices,
                            const float* __restrict__ mask,
                            const float* __restrict__ embed) {
    __shared__ int   sidx[L];
    __shared__ float smk[L];
    __shared__ float redm[8];
    int b = blockIdx.x, t = threadIdx.x, lane = t & 31, warp = t >> 5;

    if (t < L) { sidx[t] = indices[b*L + t]; smk[t] = mask[b*L + t]; }
    __syncthreads();

    float acc = 0.f;
    #pragma unroll 8
    for (int l = 0; l < L; ++l)
        acc += __ldg(embed + (size_t)sidx[l]*EDIM + t) * smk[l];

    float mv = (t < L) ? smk[t] : 0.f;
    mv = warpsum(mv);
    if (lane == 0) redm[warp] = mv;
    __syncthreads();
    float msum = redm[0]+redm[1]+redm[2]+redm[3];

    d_x[(size_t)b*EDIM + t] = acc / fmaxf(msum, 1.0f);
}

// ---------------------------------------------------------------- W gather (flat copy, max MLP)
__global__ void wgather_kernel(const int* __restrict__ labels,
                               const int* __restrict__ negidx,
                               const float* __restrict__ kernelM) {
    int id = blockIdx.x*256 + threadIdx.x;    // NW*256 threads
    int i  = id >> 8, t = id & 255;
    int j  = (i < B*KPOS) ? max(__ldg(labels + i), 0) : __ldg(negidx + i - B*KPOS);
    d_x[(size_t)(ROW_W0 + i)*EDIM + t] = __ldg(kernelM + (size_t)t*NUML + j);
}

// ---------------------------------------------------------------- featurize 8 rows per block
__global__ void __launch_bounds__(256) feat_kernel() {
    __shared__ __align__(16) float xs[EDIM*8];   // [d][g] layout, 8 KB
    __shared__ float sred[8][8], sred2[8][8];
    int base = blockIdx.x * 8;
    int t = threadIdx.x, lane = t & 31, warp = t >> 5;

    // load 8 rows (coalesced)
    float v[8];
    #pragma unroll
    for (int g = 0; g < 8; ++g) v[g] = d_x[(size_t)(base + g)*EDIM + t];

    // full-row normalize (eps 1e-4)
    #pragma unroll
    for (int g = 0; g < 8; ++g) {
        float s = warpsum(v[g]*v[g]);
        if (lane == 0) sred[g][warp] = s;
    }
    __syncthreads();
    #pragma unroll
    for (int g = 0; g < 8; ++g) {
        float tot = sred[g][0]+sred[g][1]+sred[g][2]+sred[g][3]
                  + sred[g][4]+sred[g][5]+sred[g][6]+sred[g][7];
        v[g] /= fmaxf(sqrtf(tot), 1e-4f);
    }
    // per-head normalize (eps 1e-4)
    #pragma unroll
    for (int g = 0; g < 8; ++g) {
        float s = warpsum(v[g]*v[g]);
        if (lane == 0) sred2[g][warp] = s;
    }
    __syncthreads();
    int hpair = (warp >> 1) << 1;
    #pragma unroll
    for (int g = 0; g < 8; ++g) {
        float hn = sred2[g][hpair] + sred2[g][hpair+1];
        xs[t*8 + g] = v[g] / fmaxf(sqrtf(hn), 1e-4f);
    }
    __syncthreads();

    // prf features: thread t -> (r,h,m) for all 8 rows
    {
        int r = t >> 7, h = (t >> 5) & 3;
        const float* xsh = xs + h*HD*8;
        float acc[8] = {0,0,0,0,0,0,0,0};
        #pragma unroll 8
        for (int d = 0; d < HD; ++d) {
            float om = d_omT[d*256 + t];
            float4 xa = *(const float4*)(xsh + d*8);
            float4 xb = *(const float4*)(xsh + d*8 + 4);
            acc[0] += xa.x*om; acc[1] += xa.y*om;
            acc[2] += xa.z*om; acc[3] += xa.w*om;
            acc[4] += xb.x*om; acc[5] += xb.y*om;
            acc[6] += xb.z*om; acc[7] += xb.w*om;
        }
        float s  = c_s[r];
        float sc = sqrtf(2.0f*s);
        float ml = sqrtf(c_w[r]) * INV_SQRT_M;
        #pragma unroll
        for (int g = 0; g < 8; ++g) {
            float arg = fminf(fmaxf(acc[g]*sc - s, -20.f), 20.f);
            d_prf[(size_t)(base + g)*256 + t] = expf(arg) * ml;
        }
    }

    // poly features: 512 tasks (g,hh,p), 2 per thread
    #pragma unroll
    for (int q = t; q < 512; q += 256) {
        int g = q >> 6, hh = (q >> 4) & 3, p = q & 15;
        const float* xsh = xs + hh*HD*8 + g;
        float a = 0.f;
        #pragma unroll 8
        for (int d = 0; d < HD; ++d)
            a += xsh[d*8] * d_anchT[d*P + p];
        a = fminf(fmaxf(a, -1.f), 1.f);
        d_poly[(size_t)(base + g)*64 + hh*16 + p] = a*a*0.25f;
    }
}

// ---------------------------------------------------------------- T = sum over neg rows of polyW (x) prfW
// grid = 32 chunks * 8 (r,h); each block handles 64 neg rows, atomicAdd into d_T.
__global__ void t_kernel() {
    int rh = blockIdx.x & 7;
    int chunk = blockIdx.x >> 3;
    int r = rh >> 2, h = rh & 3;
    int t = threadIdx.x;                 // 512 threads
    int p = t >> 5, m = t & 31;
    __shared__ float spw[32][16];
    __shared__ float spf[32][32];
    float acc = 0.f;
    #pragma unroll
    for (int iter = 0; iter < 2; ++iter) {
        int base = ROW_N0 + chunk*64 + iter*32;
        int lr = t >> 4, lp = t & 15;
        spw[lr][lp] = d_poly[(size_t)(base + lr)*64 + h*16 + lp];
        int fr = t >> 5, fm = t & 31;
        spf[fr     ][fm] = d_prf[(size_t)(base+fr   )*256 + r*128 + h*32 + fm];
        spf[fr + 16][fm] = d_prf[(size_t)(base+fr+16)*256 + r*128 + h*32 + fm];
        __syncthreads();
        #pragma unroll
        for (int k = 0; k < 32; ++k) acc += spw[k][p]*spf[k][m];
        __syncthreads();
    }
    atomicAdd(&d_T[rh*512 + t], acc);
}

// ---------------------------------------------------------------- per-row loss (pos scores fused in)
__global__ void rowloss_kernel(const float* __restrict__ label_mask) {
    __shared__ float spos[8];
    __shared__ float red[8];
    int b = blockIdx.x, t = threadIdx.x, lane = t & 31, warp = t >> 5;

    // --- positive score: warp w computes k=w ---
    size_t g = (size_t)(ROW_W0 + b*KPOS + warp);
    float score = 0.f;
    #pragma unroll
    for (int h = 0; h < H; ++h) {
        float pd = (lane < P) ? d_poly[(size_t)b*64 + h*16 + lane] * d_poly[g*64 + h*16 + lane] : 0.f;
        pd = warpsum(pd);
        #pragma unroll
        for (int r = 0; r < R; ++r) {
            float fd = d_prf[(size_t)b*256 + r*128 + h*32 + lane] *
                       d_prf[g*256 + r*128 + h*32 + lane];
            fd = warpsum(fd);
            score += pd * fd;
        }
    }
    if (lane == 0) spos[warp] = score;

    // --- negative row-sum via T: thread t -> (r,h,m) ---
    int r = t >> 7, h = (t >> 5) & 3, m = t & 31;
    const float* Tp = d_T + (r*4 + h)*512 + m;
    float a = 0.f;
    #pragma unroll
    for (int p = 0; p < P; ++p) a += d_poly[(size_t)b*64 + h*16 + p] * Tp[p*32];
    float val = warpsum(d_prf[(size_t)b*256 + t] * a);
    if (lane == 0) red[warp] = val;
    __syncthreads();

    if (t == 0) {
        float S = (float)NNEG * 1e-8f;
        #pragma unroll
        for (int w = 0; w < 8; ++w) S += red[w];
        #pragma unroll
        for (int k = 0; k < KPOS; ++k) S += spos[k] + 1e-8f;
        float logS = logf(S);
        float lg = 0.f;
        #pragma unroll
        for (int k = 0; k < KPOS; ++k)
            lg += label_mask[b*KPOS + k] * (logf(spos[k] + 1e-8f) - logS);
        d_numer[b] = lg;
    }
}

// ---------------------------------------------------------------- final reduction
__global__ void final_kernel(const float* __restrict__ label_mask, float* __restrict__ out) {
    __shared__ float r1[256], r2[256];
    int t = threadIdx.x;
    float a = 0.f, mm = 0.f;
    for (int i = t; i < B;      i += 256) a  += d_numer[i];
    for (int i = t; i < B*KPOS; i += 256) mm += label_mask[i];
    r1[t] = a; r2[t] = mm;
    __syncthreads();
    for (int s = 128; s > 0; s >>= 1) {
        if (t < s) { r1[t] += r1[t+s]; r2[t] += r2[t+s]; }
        __syncthreads();
    }
    if (t == 0) out[0] = -r1[0] / (r2[0] + 1e-6f);
}

// ---------------------------------------------------------------- launch
extern "C" void kernel_launch(void* const* d_in, const int* in_sizes, int n_in,
                              void* d_out, int out_size) {
    const int*   indices    = (const int*)  d_in[0];
    const float* mask       = (const float*)d_in[1];
    const int*   labels     = (const int*)  d_in[2];
    const float* label_mask = (const float*)d_in[3];
    const int*   neg_idx    = (const int*)  d_in[4];
    const float* embed      = (const float*)d_in[5];
    const float* kernelM    = (const float*)d_in[6];
    const float* omega      = (const float*)d_in[7];
    const float* anchors    = (const float*)d_in[8];
    float* out = (float*)d_out;

    prep_kernel    <<<P + 256 + 64, 64 >>>(anchors, omega);
    pool_kernel    <<<B,            256>>>(indices, mask, embed);
    wgather_kernel <<<NW,           256>>>(labels, neg_idx, kernelM);
    feat_kernel    <<<NR/8,         256>>>();
    t_kernel       <<<8*32,         512>>>();
    rowloss_kernel <<<B,            256>>>(label_mask);
    final_kernel   <<<1,            256>>>(label_mask, out);
}

// round 4
// speedup vs baseline: 1.1693x; 1.1693x over previous
#include <cuda_runtime.h>
#include <math.h>
#include <stdint.h>

// Problem constants (fixed shapes from setup_inputs)
#define B      1024
#define L      128
#define KPOS   8
#define NNEG   2048
#define NW     (B*KPOS + NNEG)   // 10240 W rows
#define NR     (B + NW)          // 11264 total rows = 352 blocks of 32
#define ROW_W0 B
#define ROW_N0 (B + B*KPOS)      // first negative row = 9216
#define EDIM   256
#define H      4
#define HD     64
#define P      16
#define M      32
#define R      2
#define NUML   131072

// Quadrature constants (double precision folded at compile time)
#define SQRT2_D 1.4142135623730951
#define CC      2.000001
__device__ __constant__ float c_s[2] = { (float)((2.0 - SQRT2_D)/CC), (float)((2.0 + SQRT2_D)/CC) };
__device__ __constant__ float c_w[2] = { (float)((2.0 + SQRT2_D)/(4.0*CC)), (float)((2.0 - SQRT2_D)/(4.0*CC)) };
#define INV_SQRT_M 0.17677669253f   // 1/sqrt(32.000001)

// Scratch (static device globals: allocation-free)
__device__ float d_anchT[HD*P];             // normalized anchors, transposed [d][p]
__device__ float d_omT  [HD*R*H*M];         // omega/8, transposed [d][r*128+h*32+m]
__device__ float d_x    [B*EDIM];           // pooled queries only
__device__ float d_poly [(size_t)NR*H*P];   // [row][h*16+p]
__device__ float d_prf  [(size_t)NR*R*H*M]; // [row][r*128+h*32+m]
__device__ float d_T    [R*H*P*M];          // [rh][p*32+m]
__device__ float d_numer[B];

__device__ __forceinline__ float warpsum(float v) {
    #pragma unroll
    for (int o = 16; o; o >>= 1) v += __shfl_xor_sync(0xffffffffu, v, o);
    return v;
}

#define FFMA2(acc, x2, o2) \
    asm("fma.rn.f32x2 %0, %1, %2, %0;" : "+l"(acc) : "l"(x2), "l"(o2))
#define PACK2(o2, f) \
    asm("mov.b64 %0, {%1, %1};" : "=l"(o2) : "r"(__float_as_uint(f)))
#define UNPACK2(lo, hi, a) \
    asm("mov.b64 {%0, %1}, %2;" : "=r"(lo), "=r"(hi) : "l"(a))

// ---------------------------------------------------------------- pool (2 q/block) + prep tail blocks
__global__ void __launch_bounds__(256) pool_prep_kernel(
        const int* __restrict__ indices, const float* __restrict__ mask,
        const float* __restrict__ embed,
        const float* __restrict__ anchors, const float* __restrict__ omega) {
    int bx = blockIdx.x, t = threadIdx.x;
    if (bx < 512) {
        __shared__ int   sidx[2][L];
        __shared__ float smk [2][L];
        __shared__ float redm[2][4];
        int q = t >> 7, c = t & 127;
        int b = bx*2 + q;
        sidx[q][c] = indices[b*L + c];
        smk [q][c] = mask   [b*L + c];
        __syncthreads();
        float mv = warpsum(smk[q][c]);
        if ((t & 31) == 0) redm[q][(t >> 5) & 3] = mv;
        __syncthreads();
        float msum = redm[q][0]+redm[q][1]+redm[q][2]+redm[q][3];
        float2 acc = make_float2(0.f, 0.f);
        const float* ebase = embed + 2*c;
        #pragma unroll 8
        for (int l = 0; l < L; ++l) {
            float2 e = *(const float2*)(ebase + (size_t)sidx[q][l]*EDIM);
            float mk = smk[q][l];
            acc.x += e.x*mk; acc.y += e.y*mk;
        }
        float inv = 1.f / fmaxf(msum, 1.0f);
        *(float2*)(d_x + b*EDIM + 2*c) = make_float2(acc.x*inv, acc.y*inv);
    } else {
        int b2 = bx - 512;
        if (b2 < 4) {                         // anchors: 4 p per block
            __shared__ float sred[8];
            int p = b2*4 + (t >> 6), d = t & 63;
            float v = anchors[p*HD + d];
            float s = warpsum(v*v);
            if ((t & 31) == 0) sred[t >> 5] = s;
            __syncthreads();
            int wp = (t >> 6)*2;
            d_anchT[d*P + p] = v / sqrtf(sred[wp] + sred[wp+1]);  // reference: no eps
        } else if (b2 < 68) {                 // omega transpose (+ /sqrt(HD) fold)
            int e = (b2 - 4)*256 + t;         // [r][h][d][m] linear
            int m = e & 31, d = (e >> 5) & 63, h = (e >> 11) & 3, r = e >> 13;
            d_omT[d*256 + r*128 + h*32 + m] = omega[e] * 0.125f;
        } else {                              // zero T
            #pragma unroll
            for (int k = 0; k < 16; ++k) d_T[k*256 + t] = 0.f;
        }
    }
}

// ---------------------------------------------------------------- fused gather + normalize + featurize
// 32 rows/block. xs layout: [c][g] stride 36 (16B-aligned vector rows, <=4-way STS conflict).
__global__ void __launch_bounds__(256, 2) feat_kernel(
        const int* __restrict__ labels, const int* __restrict__ negidx,
        const float* __restrict__ kernelM) {
    __shared__ __align__(16) float xs[EDIM*36];
    __shared__ float spart [32][8];
    __shared__ float sscale[32][4];
    __shared__ int   sj[32];
    int t = threadIdx.x, lane = t & 31, warp = t >> 5;
    int base = blockIdx.x * 32;

    if (blockIdx.x >= 32 && t < 32) {
        int i = base + t - B;
        sj[t] = (i < B*KPOS) ? max(__ldg(labels + i), 0) : __ldg(negidx + i - B*KPOS);
    }
    __syncthreads();

    float v[32];
    if (blockIdx.x < 32) {
        #pragma unroll
        for (int g = 0; g < 32; ++g) v[g] = d_x[(base + g)*EDIM + t];
    } else {
        #pragma unroll
        for (int g = 0; g < 32; ++g) v[g] = __ldg(kernelM + (size_t)t*NUML + sj[g]);
    }

    #pragma unroll
    for (int g = 0; g < 32; ++g) {
        xs[t*36 + g] = v[g];
        float s = warpsum(v[g]*v[g]);
        if (lane == 0) spart[g][warp] = s;
    }
    __syncthreads();

    if (t < 128) {     // combined full-row + per-head scale, one reduction round
        int g = t >> 2, h = t & 3;
        float tot = spart[g][0]+spart[g][1]+spart[g][2]+spart[g][3]
                  + spart[g][4]+spart[g][5]+spart[g][6]+spart[g][7];
        float hn  = spart[g][2*h] + spart[g][2*h+1];
        float S1  = fmaxf(sqrtf(tot), 1e-4f);
        float S2  = fmaxf(sqrtf(hn)/S1, 1e-4f);
        sscale[g][h] = 1.0f / (S1*S2);
    }
    __syncthreads();

    // ---- prf features: thread t -> feat col t = (r,h,m); omega in registers ----
    {
        float om[64];
        const float* omp = d_omT + t;
        #pragma unroll
        for (int d = 0; d < 64; ++d) om[d] = omp[d*256];
        int h = (t >> 5) & 3, r = t >> 7;
        const float* xsh = xs + h*64*36;
        float qs = c_s[r];
        float sc = sqrtf(2.f*qs);
        float ml = sqrtf(c_w[r]) * INV_SQRT_M;
        float* outp = d_prf + (size_t)base*256 + t;
        #pragma unroll
        for (int tile = 0; tile < 4; ++tile) {
            unsigned long long a0=0, a1=0, a2=0, a3=0;
            #pragma unroll
            for (int d = 0; d < 64; ++d) {
                unsigned long long o2; PACK2(o2, om[d]);
                const ulonglong2* xp = (const ulonglong2*)(xsh + d*36 + tile*8);
                ulonglong2 xa = xp[0], xb = xp[1];
                FFMA2(a0, xa.x, o2); FFMA2(a1, xa.y, o2);
                FFMA2(a2, xb.x, o2); FFMA2(a3, xb.y, o2);
            }
            unsigned long long aa[4] = {a0, a1, a2, a3};
            #pragma unroll
            for (int pr = 0; pr < 4; ++pr) {
                unsigned lo, hi; UNPACK2(lo, hi, aa[pr]);
                int g0 = tile*8 + pr*2;
                float f0 = __uint_as_float(lo) * sscale[g0  ][h];
                float f1 = __uint_as_float(hi) * sscale[g0+1][h];
                float e0 = __expf(fminf(fmaxf(f0*sc - qs, -20.f), 20.f)) * ml;
                float e1 = __expf(fminf(fmaxf(f1*sc - qs, -20.f), 20.f)) * ml;
                outp[(size_t)(g0  )*256] = e0;
                outp[(size_t)(g0+1)*256] = e1;
            }
        }
    }

    // ---- poly features: thread t -> (p, hh) x 8 rows; anchors in registers ----
    {
        int p = t & 15, hh = (t >> 4) & 3, slot = t >> 6;
        float an[64];
        #pragma unroll
        for (int d = 0; d < 64; ++d) an[d] = d_anchT[d*P + p];
        const float* xph = xs + hh*64*36 + slot*8;
        unsigned long long a0=0, a1=0, a2=0, a3=0;
        #pragma unroll
        for (int d = 0; d < 64; ++d) {
            unsigned long long o2; PACK2(o2, an[d]);
            const ulonglong2* xp = (const ulonglong2*)(xph + d*36);
            ulonglong2 xa = xp[0], xb = xp[1];
            FFMA2(a0, xa.x, o2); FFMA2(a1, xa.y, o2);
            FFMA2(a2, xb.x, o2); FFMA2(a3, xb.y, o2);
        }
        unsigned long long aa[4] = {a0, a1, a2, a3};
        #pragma unroll
        for (int pr = 0; pr < 4; ++pr) {
            unsigned lo, hi; UNPACK2(lo, hi, aa[pr]);
            int g0 = slot*8 + pr*2;
            float f0 = __uint_as_float(lo) * sscale[g0  ][hh];
            float f1 = __uint_as_float(hi) * sscale[g0+1][hh];
            f0 = fminf(fmaxf(f0, -1.f), 1.f);
            f1 = fminf(fmaxf(f1, -1.f), 1.f);
            d_poly[(size_t)(base + g0  )*64 + hh*16 + p] = f0*f0*0.25f;
            d_poly[(size_t)(base + g0+1)*64 + hh*16 + p] = f1*f1*0.25f;
        }
    }
}

// ---------------------------------------------------------------- T = sum over neg rows of polyW (x) prfW
__global__ void t_kernel() {
    int rh = blockIdx.x & 7, chunk = blockIdx.x >> 3;   // 8 chunks x 8 rh
    int r = rh >> 2, h = rh & 3;
    int t = threadIdx.x;                 // 512 threads
    int p = t >> 5, m = t & 31;
    __shared__ float spw[32][16];
    __shared__ float spf[32][32];
    float acc = 0.f;
    for (int iter = 0; iter < 8; ++iter) {
        int bs = ROW_N0 + chunk*256 + iter*32;
        int lr = t >> 4, lp = t & 15;
        spw[lr][lp] = d_poly[(size_t)(bs + lr)*64 + h*16 + lp];
        int fr = t >> 5, fm = t & 31;
        spf[fr     ][fm] = d_prf[(size_t)(bs+fr   )*256 + r*128 + h*32 + fm];
        spf[fr + 16][fm] = d_prf[(size_t)(bs+fr+16)*256 + r*128 + h*32 + fm];
        __syncthreads();
        #pragma unroll
        for (int k = 0; k < 32; ++k) acc += spw[k][p]*spf[k][m];
        __syncthreads();
    }
    atomicAdd(&d_T[rh*512 + t], acc);
}

// ---------------------------------------------------------------- per-row loss (pos scores fused in)
__global__ void rowloss_kernel(const float* __restrict__ label_mask) {
    __shared__ float spos[8];
    __shared__ float red[8];
    int b = blockIdx.x, t = threadIdx.x, lane = t & 31, warp = t >> 5;

    size_t g = (size_t)(ROW_W0 + b*KPOS + warp);
    float score = 0.f;
    #pragma unroll
    for (int h = 0; h < H; ++h) {
        float pd = (lane < P) ? d_poly[(size_t)b*64 + h*16 + lane] * d_poly[g*64 + h*16 + lane] : 0.f;
        pd = warpsum(pd);
        #pragma unroll
        for (int r = 0; r < R; ++r) {
            float fd = d_prf[(size_t)b*256 + r*128 + h*32 + lane] *
                       d_prf[g*256 + r*128 + h*32 + lane];
            fd = warpsum(fd);
            score += pd * fd;
        }
    }
    if (lane == 0) spos[warp] = score;

    int r = t >> 7, h = (t >> 5) & 3, m = t & 31;
    const float* Tp = d_T + (r*4 + h)*512 + m;
    float a = 0.f;
    #pragma unroll
    for (int p = 0; p < P; ++p) a += d_poly[(size_t)b*64 + h*16 + p] * Tp[p*32];
    float val = warpsum(d_prf[(size_t)b*256 + t] * a);
    if (lane == 0) red[warp] = val;
    __syncthreads();

    if (t == 0) {
        float S = (float)NNEG * 1e-8f;
        #pragma unroll
        for (int w = 0; w < 8; ++w) S += red[w];
        #pragma unroll
        for (int k = 0; k < KPOS; ++k) S += spos[k] + 1e-8f;
        float logS = logf(S);
        float lg = 0.f;
        #pragma unroll
        for (int k = 0; k < KPOS; ++k)
            lg += label_mask[b*KPOS + k] * (logf(spos[k] + 1e-8f) - logS);
        d_numer[b] = lg;
    }
}

// ---------------------------------------------------------------- final reduction
__global__ void final_kernel(const float* __restrict__ label_mask, float* __restrict__ out) {
    __shared__ float r1[256], r2[256];
    int t = threadIdx.x;
    float a = 0.f, mm = 0.f;
    for (int i = t; i < B;      i += 256) a  += d_numer[i];
    for (int i = t; i < B*KPOS; i += 256) mm += label_mask[i];
    r1[t] = a; r2[t] = mm;
    __syncthreads();
    for (int s = 128; s > 0; s >>= 1) {
        if (t < s) { r1[t] += r1[t+s]; r2[t] += r2[t+s]; }
        __syncthreads();
    }
    if (t == 0) out[0] = -r1[0] / (r2[0] + 1e-6f);
}

// ---------------------------------------------------------------- launch
extern "C" void kernel_launch(void* const* d_in, const int* in_sizes, int n_in,
                              void* d_out, int out_size) {
    const int*   indices    = (const int*)  d_in[0];
    const float* mask       = (const float*)d_in[1];
    const int*   labels     = (const int*)  d_in[2];
    const float* label_mask = (const float*)d_in[3];
    const int*   neg_idx    = (const int*)  d_in[4];
    const float* embed      = (const float*)d_in[5];
    const float* kernelM    = (const float*)d_in[6];
    const float* omega      = (const float*)d_in[7];
    const float* anchors    = (const float*)d_in[8];
    float* out = (float*)d_out;

    pool_prep_kernel<<<581,   256>>>(indices, mask, embed, anchors, omega);
    feat_kernel     <<<NR/32, 256>>>(labels, neg_idx, kernelM);
    t_kernel        <<<64,    512>>>();
    rowloss_kernel  <<<B,     256>>>(label_mask);
    final_kernel    <<<1,     256>>>(label_mask, out);
}